// round 1
// baseline (speedup 1.0000x reference)
#include <cuda_runtime.h>
#include <cuda_bf16.h>
#include <stdint.h>
#include <stddef.h>

#define BB 2048
#define CC 50000
#define DD 128
#define S_SCALE 20.0f
#define MARGIN 0.1f
#define CLAMP_EPS 1e-7f

#define TILE_M 128
#define TILE_N 128
#define NT_C ((CC + TILE_N - 1) / TILE_N)   // 391
#define NT_M (BB / TILE_M)                  // 16
#define PITCH 136                           // bf16 elems per smem row (128 + 8 pad)
#define SMEM_BYTES (2 * TILE_M * PITCH * 2) // 69632 bytes

// ---------------- scratch (static device memory; no allocations) ----------------
__device__ __align__(16) __nv_bfloat16 g_e_bf16[BB * DD];
__device__ __align__(16) float         g_e_f32 [BB * DD];
__device__ __align__(16) __nv_bfloat16 g_W_bf16[CC * DD];
__device__ __align__(16) float g_partial_p[NT_C * BB];  // per C-tile partial sums of exp(wf)
__device__ __align__(16) float g_partial_q[NT_C * BB];  // per C-tile partial sums of exp(wf)^20
__device__ float g_rowsum_q[BB];
__device__ float g_inv_p  [BB];
__device__ float g_lossrow[BB];

// ---------------- helpers ----------------
__device__ __forceinline__ float warp_sum(float v) {
    #pragma unroll
    for (int o = 16; o; o >>= 1) v += __shfl_xor_sync(0xffffffffu, v, o);
    return v;
}

__device__ __forceinline__ float pow20(float p) {
    float p2 = p * p, p4 = p2 * p2, p8 = p4 * p4, p16 = p8 * p8;
    return p16 * p4;
}

__device__ __forceinline__ void mma16816(float* c, const uint32_t* a, const uint32_t* b) {
    asm volatile(
        "mma.sync.aligned.m16n8k16.row.col.f32.bf16.bf16.f32 "
        "{%0,%1,%2,%3}, {%4,%5,%6,%7}, {%8,%9}, {%0,%1,%2,%3};\n"
        : "+f"(c[0]), "+f"(c[1]), "+f"(c[2]), "+f"(c[3])
        : "r"(a[0]), "r"(a[1]), "r"(a[2]), "r"(a[3]), "r"(b[0]), "r"(b[1]));
}

// ---------------- K1: normalize x -> e (f32 + bf16) ----------------
__global__ void k_norm_x(const float* __restrict__ x) {
    int warp = (blockIdx.x * blockDim.x + threadIdx.x) >> 5;
    int lane = threadIdx.x & 31;
    if (warp >= BB) return;
    float4 v = ((const float4*)(x + (size_t)warp * DD))[lane];
    float ss = warp_sum(v.x * v.x + v.y * v.y + v.z * v.z + v.w * v.w);
    float inv = 1.0f / fmaxf(sqrtf(ss), 1e-12f);
    float4 e = make_float4(v.x * inv, v.y * inv, v.z * inv, v.w * inv);
    ((float4*)(g_e_f32 + (size_t)warp * DD))[lane] = e;
    __nv_bfloat162* eb = (__nv_bfloat162*)(g_e_bf16 + (size_t)warp * DD);
    eb[lane * 2 + 0] = __floats2bfloat162_rn(e.x, e.y);
    eb[lane * 2 + 1] = __floats2bfloat162_rn(e.z, e.w);
}

// ---------------- K2: normalize W -> Wn (bf16) ----------------
__global__ void k_norm_w(const float* __restrict__ W) {
    int warp = (blockIdx.x * blockDim.x + threadIdx.x) >> 5;
    int lane = threadIdx.x & 31;
    if (warp >= CC) return;
    float4 v = ((const float4*)(W + (size_t)warp * DD))[lane];
    float ss = warp_sum(v.x * v.x + v.y * v.y + v.z * v.z + v.w * v.w);
    float inv = 1.0f / fmaxf(sqrtf(ss), 1e-12f);
    __nv_bfloat162* wb = (__nv_bfloat162*)(g_W_bf16 + (size_t)warp * DD);
    wb[lane * 2 + 0] = __floats2bfloat162_rn(v.x * inv, v.y * inv);
    wb[lane * 2 + 1] = __floats2bfloat162_rn(v.z * inv, v.w * inv);
}

// ---------------- K3/K6: GEMM (e @ Wn^T), two epilogues ----------------
extern __shared__ char smem_raw[];

__global__ __launch_bounds__(256, 2) void k_gemm(const float* __restrict__ bias,
                                                 float* __restrict__ out, int pass) {
    const int tc = blockIdx.x;          // C tile
    const int tm = blockIdx.y;          // B tile
    __nv_bfloat16* As = (__nv_bfloat16*)smem_raw;
    __nv_bfloat16* Bs = As + TILE_M * PITCH;
    const int tid = threadIdx.x;
    const int colBase = tc * TILE_N;

    // load A tile: 128 rows x 128 bf16 (16 uint4 per row)
    {
        const uint4* gA = (const uint4*)(g_e_bf16 + (size_t)tm * TILE_M * DD);
        #pragma unroll
        for (int i = tid; i < TILE_M * DD / 8; i += 256) {
            int row = i >> 4, seg = i & 15;
            *(uint4*)(As + row * PITCH + seg * 8) = gA[row * 16 + seg];
        }
    }
    // load B tile: 128 "rows" (classes) x 128 bf16, guarded
    {
        #pragma unroll
        for (int i = tid; i < TILE_N * DD / 8; i += 256) {
            int row = i >> 4, seg = i & 15;
            int gcol = colBase + row;
            uint4 v = make_uint4(0u, 0u, 0u, 0u);
            if (gcol < CC) v = *(const uint4*)(g_W_bf16 + (size_t)gcol * DD + seg * 8);
            *(uint4*)(Bs + row * PITCH + seg * 8) = v;
        }
    }
    __syncthreads();

    const int wid = tid >> 5, lane = tid & 31;
    const int wm = wid & 3, wn = wid >> 2;   // 4 x 2 warp grid: 32 rows x 64 cols each
    const int g = lane >> 2, s = lane & 3;

    float acc[2][8][4];
    #pragma unroll
    for (int mt = 0; mt < 2; mt++)
        #pragma unroll
        for (int nt = 0; nt < 8; nt++)
            #pragma unroll
            for (int k = 0; k < 4; k++) acc[mt][nt][k] = 0.0f;

    #pragma unroll
    for (int ks = 0; ks < 8; ks++) {
        const int k0 = ks * 16;
        uint32_t a[2][4], b[8][2];
        #pragma unroll
        for (int mt = 0; mt < 2; mt++) {
            const __nv_bfloat16* pa = As + (wm * 32 + mt * 16 + g) * PITCH + k0 + 2 * s;
            a[mt][0] = *(const uint32_t*)pa;
            a[mt][1] = *(const uint32_t*)(pa + 8 * PITCH);
            a[mt][2] = *(const uint32_t*)(pa + 8);
            a[mt][3] = *(const uint32_t*)(pa + 8 * PITCH + 8);
        }
        #pragma unroll
        for (int nt = 0; nt < 8; nt++) {
            const __nv_bfloat16* pb = Bs + (wn * 64 + nt * 8 + g) * PITCH + k0 + 2 * s;
            b[nt][0] = *(const uint32_t*)pb;
            b[nt][1] = *(const uint32_t*)(pb + 8);
        }
        #pragma unroll
        for (int mt = 0; mt < 2; mt++)
            #pragma unroll
            for (int nt = 0; nt < 8; nt++)
                mma16816(acc[mt][nt], a[mt], b[nt]);
    }

    const int rowG = tm * TILE_M + wm * 32;   // global row base of this warp

    if (pass == 1) {
        // accumulate row sums of p = exp(wf) and q = p^20 over this tile
        float sp[4] = {0, 0, 0, 0}, sq[4] = {0, 0, 0, 0};
        #pragma unroll
        for (int nt = 0; nt < 8; nt++) {
            int c0 = colBase + wn * 64 + nt * 8 + 2 * s;
            if (c0 >= CC) continue;   // CC even, pair fully in/out
            float b0v = bias[c0], b1v = bias[c0 + 1];
            #pragma unroll
            for (int mt = 0; mt < 2; mt++) {
                float p00 = __expf(acc[mt][nt][0] + b0v);
                float p01 = __expf(acc[mt][nt][1] + b1v);
                float p10 = __expf(acc[mt][nt][2] + b0v);
                float p11 = __expf(acc[mt][nt][3] + b1v);
                sp[mt * 2 + 0] += p00 + p01;
                sp[mt * 2 + 1] += p10 + p11;
                sq[mt * 2 + 0] += pow20(p00) + pow20(p01);
                sq[mt * 2 + 1] += pow20(p10) + pow20(p11);
            }
        }
        // reduce over the 4 lanes of each row group (s dimension)
        #pragma unroll
        for (int j = 0; j < 4; j++) {
            sp[j] += __shfl_xor_sync(0xffffffffu, sp[j], 1);
            sp[j] += __shfl_xor_sync(0xffffffffu, sp[j], 2);
            sq[j] += __shfl_xor_sync(0xffffffffu, sq[j], 1);
            sq[j] += __shfl_xor_sync(0xffffffffu, sq[j], 2);
        }
        __syncthreads();   // smem tiles no longer needed; reuse for reduction
        float* sredP = (float*)smem_raw;        // [2][128]
        float* sredQ = sredP + 256;             // [2][128]
        if (s == 0) {
            #pragma unroll
            for (int mt = 0; mt < 2; mt++) {
                #pragma unroll
                for (int h = 0; h < 2; h++) {
                    int r = wm * 32 + mt * 16 + g + 8 * h;
                    sredP[wn * 128 + r] = sp[mt * 2 + h];
                    sredQ[wn * 128 + r] = sq[mt * 2 + h];
                }
            }
        }
        __syncthreads();
        if (tid < 128) {
            g_partial_p[(size_t)tc * BB + tm * TILE_M + tid] = sredP[tid] + sredP[128 + tid];
            g_partial_q[(size_t)tc * BB + tm * TILE_M + tid] = sredQ[tid] + sredQ[128 + tid];
        }
    } else {
        // pass 2: write prediction = exp(wf) * inv_rowsum
        float inv0[2], inv1[2];
        #pragma unroll
        for (int mt = 0; mt < 2; mt++) {
            inv0[mt] = g_inv_p[rowG + mt * 16 + g];
            inv1[mt] = g_inv_p[rowG + mt * 16 + g + 8];
        }
        #pragma unroll
        for (int nt = 0; nt < 8; nt++) {
            int c0 = colBase + wn * 64 + nt * 8 + 2 * s;
            if (c0 >= CC) continue;
            float b0v = bias[c0], b1v = bias[c0 + 1];
            #pragma unroll
            for (int mt = 0; mt < 2; mt++) {
                int r0 = rowG + mt * 16 + g;
                float2 o0 = make_float2(__expf(acc[mt][nt][0] + b0v) * inv0[mt],
                                        __expf(acc[mt][nt][1] + b1v) * inv0[mt]);
                float2 o1 = make_float2(__expf(acc[mt][nt][2] + b0v) * inv1[mt],
                                        __expf(acc[mt][nt][3] + b1v) * inv1[mt]);
                *(float2*)(out + (size_t)r0 * CC + c0)       = o0;
                *(float2*)(out + (size_t)(r0 + 8) * CC + c0) = o1;
            }
        }
    }
}

// ---------------- K4: deterministic row reduce over C tiles ----------------
__global__ void k_reduce_rows() {
    int r = blockIdx.x * blockDim.x + threadIdx.x;
    if (r >= BB) return;
    float sp = 0.0f, sq = 0.0f;
    for (int t = 0; t < NT_C; t++) {
        sp += g_partial_p[(size_t)t * BB + r];
        sq += g_partial_q[(size_t)t * BB + r];
    }
    g_inv_p[r]    = 1.0f / sp;
    g_rowsum_q[r] = sq;
}

// ---------------- K5: per-row ArcFace margin + loss term ----------------
__global__ void k_label(const float* __restrict__ W, const float* __restrict__ bias,
                        const int* __restrict__ labels) {
    int warp = (blockIdx.x * blockDim.x + threadIdx.x) >> 5;
    int lane = threadIdx.x & 31;
    if (warp >= BB) return;
    int l = labels[warp];

    float4 wv = ((const float4*)(W + (size_t)l * DD))[lane];
    float ss = warp_sum(wv.x * wv.x + wv.y * wv.y + wv.z * wv.z + wv.w * wv.w);
    float invn = 1.0f / fmaxf(sqrtf(ss), 1e-12f);

    float4 ev = ((const float4*)(g_e_f32 + (size_t)warp * DD))[lane];
    float d = warp_sum(ev.x * wv.x + ev.y * wv.y + ev.z * wv.z + ev.w * wv.w) * invn;

    // bf16-path dot (matches the GEMM inputs) for exact-term removal from the sum
    const __nv_bfloat162* eb = (const __nv_bfloat162*)(g_e_bf16 + (size_t)warp * DD);
    const __nv_bfloat162* wb = (const __nv_bfloat162*)(g_W_bf16 + (size_t)l * DD);
    float db = 0.0f;
    #pragma unroll
    for (int j = 0; j < 2; j++) {
        float2 e2 = __bfloat1622float2(eb[lane * 2 + j]);
        float2 w2 = __bfloat1622float2(wb[lane * 2 + j]);
        db += e2.x * w2.x + e2.y * w2.y;
    }
    db = warp_sum(db);

    if (lane == 0) {
        float bl = bias[l];
        float wf_f = d + bl;          // accurate logit at label
        float wf_b = db + bl;         // bf16-path logit at label (as in GEMM sums)
        float cth = fminf(fmaxf(wf_f, -1.0f + CLAMP_EPS), 1.0f - CLAMP_EPS);
        float cm = cth * cosf(MARGIN) - sqrtf(fmaxf(1.0f - cth * cth, 0.0f)) * sinf(MARGIN);
        float Z = g_rowsum_q[warp] - __expf(S_SCALE * wf_b) + __expf(S_SCALE * cm);
        g_lossrow[warp] = logf(Z) - S_SCALE * cm;
    }
}

// ---------------- K7: finalize loss ----------------
__global__ void k_final(float* __restrict__ out, int out_size) {
    __shared__ float sh[256];
    float v = 0.0f;
    for (int i = threadIdx.x; i < BB; i += 256) v += g_lossrow[i];
    sh[threadIdx.x] = v;
    __syncthreads();
    for (int o = 128; o; o >>= 1) {
        if (threadIdx.x < o) sh[threadIdx.x] += sh[threadIdx.x + o];
        __syncthreads();
    }
    if (threadIdx.x == 0) out[out_size - 1] = sh[0] / (float)BB;
}

// ---------------- launch ----------------
extern "C" void kernel_launch(void* const* d_in, const int* in_sizes, int n_in,
                              void* d_out, int out_size) {
    const float* x      = (const float*)d_in[0];
    const float* W      = (const float*)d_in[1];
    const float* bias   = (const float*)d_in[2];
    const int*   labels = (const int*)d_in[3];
    float* out = (float*)d_out;

    cudaFuncSetAttribute((const void*)k_gemm,
                         cudaFuncAttributeMaxDynamicSharedMemorySize, SMEM_BYTES);

    k_norm_x<<<BB / 8, 256>>>(x);
    k_norm_w<<<(CC + 7) / 8, 256>>>(W);
    k_gemm<<<dim3(NT_C, NT_M), 256, SMEM_BYTES>>>(bias, out, 1);
    k_reduce_rows<<<BB / 256, 256>>>();
    k_label<<<BB / 8, 256>>>(W, bias, labels);
    k_gemm<<<dim3(NT_C, NT_M), 256, SMEM_BYTES>>>(bias, out, 2);
    k_final<<<1, 256>>>(out, out_size);
}

// round 5
// speedup vs baseline: 1.0733x; 1.0733x over previous
#include <cuda_runtime.h>
#include <cuda_fp16.h>
#include <stdint.h>
#include <stddef.h>

#define BB 2048
#define CC 50000
#define DD 128
#define S_SCALE 20.0f
#define MARGIN 0.1f
#define CLAMP_EPS 1e-7f

#define TILE_M 128
#define TILE_N 128
#define NT_C ((CC + TILE_N - 1) / TILE_N)   // 391
#define NT_M (BB / TILE_M)                  // 16
#define PITCH 136                           // halfs per smem row (128 + 8 pad) -> 272 bytes
#define SMEM_TILES_BYTES (2 * TILE_M * PITCH * 2)          // 69632 bytes of A+B tiles
#define SMEM_BYTES (SMEM_TILES_BYTES + TILE_N * 4)         // + bias tile

// ---------------- scratch ----------------
__device__ __align__(16) __half g_e_h  [BB * DD];
__device__ __align__(16) float  g_e_f32[BB * DD];
__device__ __align__(16) __half g_W_h  [CC * DD];
__device__ __align__(16) float g_partial_p[NT_C * BB];
__device__ __align__(16) float g_partial_q[NT_C * BB];
__device__ float g_rowsum_q[BB];
__device__ float g_inv_p  [BB];
__device__ float g_lossrow[BB];

// ---------------- helpers ----------------
__device__ __forceinline__ uint32_t smem_u32(const void* p) {
    uint32_t a;
    asm("{ .reg .u64 t; cvta.to.shared.u64 t, %1; cvt.u32.u64 %0, t; }" : "=r"(a) : "l"(p));
    return a;
}
__device__ __forceinline__ float warp_sum(float v) {
    #pragma unroll
    for (int o = 16; o; o >>= 1) v += __shfl_xor_sync(0xffffffffu, v, o);
    return v;
}
__device__ __forceinline__ float pow20(float p) {
    float p2 = p * p, p4 = p2 * p2, p8 = p4 * p4, p16 = p8 * p8;
    return p16 * p4;
}
__device__ __forceinline__ void mma16816(float* c, const uint32_t* a, uint32_t b0, uint32_t b1) {
    asm volatile(
        "mma.sync.aligned.m16n8k16.row.col.f32.f16.f16.f32 "
        "{%0,%1,%2,%3}, {%4,%5,%6,%7}, {%8,%9}, {%0,%1,%2,%3};\n"
        : "+f"(c[0]), "+f"(c[1]), "+f"(c[2]), "+f"(c[3])
        : "r"(a[0]), "r"(a[1]), "r"(a[2]), "r"(a[3]), "r"(b0), "r"(b1));
}
__device__ __forceinline__ void ldsm_x4(uint32_t* r, uint32_t addr) {
    asm volatile("ldmatrix.sync.aligned.m8n8.x4.shared.b16 {%0,%1,%2,%3}, [%4];"
                 : "=r"(r[0]), "=r"(r[1]), "=r"(r[2]), "=r"(r[3]) : "r"(addr));
}

// ---------------- K1: normalize x ----------------
__global__ void k_norm_x(const float* __restrict__ x) {
    int warp = (blockIdx.x * blockDim.x + threadIdx.x) >> 5;
    int lane = threadIdx.x & 31;
    if (warp >= BB) return;
    float4 v = ((const float4*)(x + (size_t)warp * DD))[lane];
    float ss = warp_sum(v.x * v.x + v.y * v.y + v.z * v.z + v.w * v.w);
    float inv = 1.0f / fmaxf(sqrtf(ss), 1e-12f);
    float4 e = make_float4(v.x * inv, v.y * inv, v.z * inv, v.w * inv);
    ((float4*)(g_e_f32 + (size_t)warp * DD))[lane] = e;
    __half2* eb = (__half2*)(g_e_h + (size_t)warp * DD);
    eb[lane * 2 + 0] = __floats2half2_rn(e.x, e.y);
    eb[lane * 2 + 1] = __floats2half2_rn(e.z, e.w);
}

// ---------------- K2: normalize W ----------------
__global__ void k_norm_w(const float* __restrict__ W) {
    int warp = (blockIdx.x * blockDim.x + threadIdx.x) >> 5;
    int lane = threadIdx.x & 31;
    if (warp >= CC) return;
    float4 v = ((const float4*)(W + (size_t)warp * DD))[lane];
    float ss = warp_sum(v.x * v.x + v.y * v.y + v.z * v.z + v.w * v.w);
    float inv = 1.0f / fmaxf(sqrtf(ss), 1e-12f);
    __half2* wb = (__half2*)(g_W_h + (size_t)warp * DD);
    wb[lane * 2 + 0] = __floats2half2_rn(v.x * inv, v.y * inv);
    wb[lane * 2 + 1] = __floats2half2_rn(v.z * inv, v.w * inv);
}

// ---------------- K3: single GEMM pass: p -> out, partials -> scratch ----------------
extern __shared__ char smem_raw[];

__global__ __launch_bounds__(256, 2) void k_gemm(const float* __restrict__ bias,
                                                 float* __restrict__ out) {
    const int tc = blockIdx.x;          // C tile
    const int tm = blockIdx.y;          // B tile
    __half* As = (__half*)smem_raw;
    __half* Bs = As + TILE_M * PITCH;
    float* sBias = (float*)(smem_raw + SMEM_TILES_BYTES);   // byte offset (bugfix)
    const int tid = threadIdx.x;
    const int colBase = tc * TILE_N;

    if (tid < TILE_N) {
        int col = colBase + tid;
        sBias[tid] = (col < CC) ? bias[col] : 0.0f;
    }
    // A tile: 128 rows x 128 halfs
    {
        const uint4* gA = (const uint4*)(g_e_h + (size_t)tm * TILE_M * DD);
        #pragma unroll
        for (int i = tid; i < TILE_M * DD / 8; i += 256) {
            int row = i >> 4, seg = i & 15;
            *(uint4*)(As + row * PITCH + seg * 8) = gA[row * 16 + seg];
        }
    }
    // B tile: 128 classes x 128 halfs, guarded
    {
        #pragma unroll
        for (int i = tid; i < TILE_N * DD / 8; i += 256) {
            int row = i >> 4, seg = i & 15;
            int gcol = colBase + row;
            uint4 v = make_uint4(0u, 0u, 0u, 0u);
            if (gcol < CC) v = *(const uint4*)(g_W_h + (size_t)gcol * DD + seg * 8);
            *(uint4*)(Bs + row * PITCH + seg * 8) = v;
        }
    }
    __syncthreads();

    const int wid = tid >> 5, lane = tid & 31;
    const int wm = wid & 3, wn = wid >> 2;   // 4 x 2 warp grid: 32 rows x 64 cols each
    const int g = lane >> 2, s = lane & 3;

    // ldmatrix lane addresses (byte offsets; row pitch 272B)
    const uint32_t sbase = smem_u32(smem_raw);
    const uint32_t aBase = sbase;
    const uint32_t bBase = sbase + TILE_M * PITCH * 2;
    uint32_t aAddr[2], bAddr[4];
    {
        int ar = wm * 32 + (lane & 15);
        int ak = (lane & 16) ? 16 : 0;          // +8 halfs = 16B
        aAddr[0] = aBase + ar * (PITCH * 2) + ak;
        aAddr[1] = aAddr[0] + 16 * (PITCH * 2);
        int brl = (lane & 7) + ((lane & 16) ? 8 : 0);
        int bk  = (lane & 8) ? 16 : 0;
        #pragma unroll
        for (int p = 0; p < 4; p++)
            bAddr[p] = bBase + (wn * 64 + p * 16 + brl) * (PITCH * 2) + bk;
    }

    float acc[2][8][4];
    #pragma unroll
    for (int mt = 0; mt < 2; mt++)
        #pragma unroll
        for (int nt = 0; nt < 8; nt++)
            #pragma unroll
            for (int k = 0; k < 4; k++) acc[mt][nt][k] = 0.0f;

    #pragma unroll
    for (int ks = 0; ks < 8; ks++) {
        const uint32_t koff = ks * 32;          // 16 halfs
        uint32_t a[2][4], bq[4][4];
        #pragma unroll
        for (int mt = 0; mt < 2; mt++) ldsm_x4(a[mt], aAddr[mt] + koff);
        #pragma unroll
        for (int p = 0; p < 4; p++) ldsm_x4(bq[p], bAddr[p] + koff);
        #pragma unroll
        for (int mt = 0; mt < 2; mt++)
            #pragma unroll
            for (int nt = 0; nt < 8; nt++) {
                int p = nt >> 1;
                if (nt & 1) mma16816(acc[mt][nt], a[mt], bq[p][2], bq[p][3]);
                else        mma16816(acc[mt][nt], a[mt], bq[p][0], bq[p][1]);
            }
    }

    const int rowG = tm * TILE_M + wm * 32;

    // epilogue: p = exp(wf) -> out (unnormalized), accumulate row partials of p, p^20
    float sp[4] = {0, 0, 0, 0}, sq[4] = {0, 0, 0, 0};
    #pragma unroll
    for (int nt = 0; nt < 8; nt++) {
        int cl = wn * 64 + nt * 8 + 2 * s;
        int c0 = colBase + cl;
        if (c0 >= CC) continue;                 // CC even -> pair fully in/out
        float b0v = sBias[cl], b1v = sBias[cl + 1];
        #pragma unroll
        for (int mt = 0; mt < 2; mt++) {
            float p00 = __expf(acc[mt][nt][0] + b0v);
            float p01 = __expf(acc[mt][nt][1] + b1v);
            float p10 = __expf(acc[mt][nt][2] + b0v);
            float p11 = __expf(acc[mt][nt][3] + b1v);
            int r0 = rowG + mt * 16 + g;
            float2 o0 = make_float2(p00, p01);
            float2 o1 = make_float2(p10, p11);
            __stcs((float2*)(out + (size_t)r0 * CC + c0), o0);
            __stcs((float2*)(out + (size_t)(r0 + 8) * CC + c0), o1);
            sp[mt * 2 + 0] += p00 + p01;
            sp[mt * 2 + 1] += p10 + p11;
            sq[mt * 2 + 0] += pow20(p00) + pow20(p01);
            sq[mt * 2 + 1] += pow20(p10) + pow20(p11);
        }
    }
    #pragma unroll
    for (int j = 0; j < 4; j++) {
        sp[j] += __shfl_xor_sync(0xffffffffu, sp[j], 1);
        sp[j] += __shfl_xor_sync(0xffffffffu, sp[j], 2);
        sq[j] += __shfl_xor_sync(0xffffffffu, sq[j], 1);
        sq[j] += __shfl_xor_sync(0xffffffffu, sq[j], 2);
    }
    __syncthreads();                            // tiles no longer needed; reuse smem
    float* sredP = (float*)smem_raw;            // [2][128]
    float* sredQ = sredP + 256;                 // [2][128]
    if (s == 0) {
        #pragma unroll
        for (int mt = 0; mt < 2; mt++)
            #pragma unroll
            for (int h = 0; h < 2; h++) {
                int r = wm * 32 + mt * 16 + g + 8 * h;
                sredP[wn * 128 + r] = sp[mt * 2 + h];
                sredQ[wn * 128 + r] = sq[mt * 2 + h];
            }
    }
    __syncthreads();
    if (tid < 128) {
        g_partial_p[(size_t)tc * BB + tm * TILE_M + tid] = sredP[tid] + sredP[128 + tid];
        g_partial_q[(size_t)tc * BB + tm * TILE_M + tid] = sredQ[tid] + sredQ[128 + tid];
    }
}

// ---------------- K4: warp-per-row reduce over C tiles ----------------
__global__ void k_reduce_rows() {
    int warp = (blockIdx.x * blockDim.x + threadIdx.x) >> 5;
    int lane = threadIdx.x & 31;
    if (warp >= BB) return;
    float sp = 0.0f, sq = 0.0f;
    for (int t = lane; t < NT_C; t += 32) {
        sp += g_partial_p[(size_t)t * BB + warp];
        sq += g_partial_q[(size_t)t * BB + warp];
    }
    sp = warp_sum(sp);
    sq = warp_sum(sq);
    if (lane == 0) {
        g_inv_p[warp]    = 1.0f / sp;
        g_rowsum_q[warp] = sq;
    }
}

// ---------------- K5: label margin + per-row loss ----------------
__global__ void k_label(const float* __restrict__ W, const float* __restrict__ bias,
                        const int* __restrict__ labels) {
    int warp = (blockIdx.x * blockDim.x + threadIdx.x) >> 5;
    int lane = threadIdx.x & 31;
    if (warp >= BB) return;
    int l = labels[warp];

    float4 wv = ((const float4*)(W + (size_t)l * DD))[lane];
    float ss = warp_sum(wv.x * wv.x + wv.y * wv.y + wv.z * wv.z + wv.w * wv.w);
    float invn = 1.0f / fmaxf(sqrtf(ss), 1e-12f);

    float4 ev = ((const float4*)(g_e_f32 + (size_t)warp * DD))[lane];
    float d = warp_sum(ev.x * wv.x + ev.y * wv.y + ev.z * wv.z + ev.w * wv.w) * invn;

    // fp16-path dot (matches GEMM inputs) for exact-term removal from the sum
    const __half2* eb = (const __half2*)(g_e_h + (size_t)warp * DD);
    const __half2* wb = (const __half2*)(g_W_h + (size_t)l * DD);
    float db = 0.0f;
    #pragma unroll
    for (int j = 0; j < 2; j++) {
        float2 e2 = __half22float2(eb[lane * 2 + j]);
        float2 w2 = __half22float2(wb[lane * 2 + j]);
        db += e2.x * w2.x + e2.y * w2.y;
    }
    db = warp_sum(db);

    if (lane == 0) {
        float bl = bias[l];
        float wf_f = d + bl;
        float wf_b = db + bl;
        float cth = fminf(fmaxf(wf_f, -1.0f + CLAMP_EPS), 1.0f - CLAMP_EPS);
        float cm = cth * cosf(MARGIN) - sqrtf(fmaxf(1.0f - cth * cth, 0.0f)) * sinf(MARGIN);
        float Z = g_rowsum_q[warp] - __expf(S_SCALE * wf_b) + __expf(S_SCALE * cm);
        g_lossrow[warp] = logf(Z) - S_SCALE * cm;
    }
}

// ---------------- K6: in-place normalize (streaming) ----------------
__global__ __launch_bounds__(256) void k_scale(float* __restrict__ out) {
    int idx = blockIdx.x * 256 + threadIdx.x;    // one float4 per thread
    int row = idx / (CC / 4);                     // CC/4 = 12500 float4 per row
    float inv = __ldg(&g_inv_p[row]);
    float4* p4 = (float4*)out;
    float4 v = p4[idx];
    v.x *= inv; v.y *= inv; v.z *= inv; v.w *= inv;
    p4[idx] = v;
}

// ---------------- K7: finalize loss ----------------
__global__ void k_final(float* __restrict__ out, int out_size) {
    __shared__ float sh[256];
    float v = 0.0f;
    for (int i = threadIdx.x; i < BB; i += 256) v += g_lossrow[i];
    sh[threadIdx.x] = v;
    __syncthreads();
    for (int o = 128; o; o >>= 1) {
        if (threadIdx.x < o) sh[threadIdx.x] += sh[threadIdx.x + o];
        __syncthreads();
    }
    if (threadIdx.x == 0) out[out_size - 1] = sh[0] / (float)BB;
}

// ---------------- launch ----------------
extern "C" void kernel_launch(void* const* d_in, const int* in_sizes, int n_in,
                              void* d_out, int out_size) {
    const float* x      = (const float*)d_in[0];
    const float* W      = (const float*)d_in[1];
    const float* bias   = (const float*)d_in[2];
    const int*   labels = (const int*)d_in[3];
    float* out = (float*)d_out;

    cudaFuncSetAttribute((const void*)k_gemm,
                         cudaFuncAttributeMaxDynamicSharedMemorySize, SMEM_BYTES);

    k_norm_x<<<BB / 8, 256>>>(x);
    k_norm_w<<<(CC + 7) / 8, 256>>>(W);
    k_gemm<<<dim3(NT_C, NT_M), 256, SMEM_BYTES>>>(bias, out);
    k_reduce_rows<<<BB * 32 / 256, 256>>>();
    k_label<<<BB / 8, 256>>>(W, bias, labels);
    k_scale<<<BB * CC / 4 / 256, 256>>>(out);
    k_final<<<1, 256>>>(out, out_size);
}

// round 6
// speedup vs baseline: 1.2037x; 1.1215x over previous
#include <cuda_runtime.h>
#include <cuda_fp16.h>
#include <stdint.h>
#include <stddef.h>

#define BB 2048
#define CC 50000
#define DD 128
#define S_SCALE 20.0f
#define MARGIN 0.1f
#define CLAMP_EPS 1e-7f

#define TILE_M 128
#define TILE_N 128
#define NT_C ((CC + TILE_N - 1) / TILE_N)   // 391
#define NT_M (BB / TILE_M)                  // 16
#define PITCH 136                           // halfs per smem row (128 + 8 pad) -> 272 bytes
#define SMEM_TILES_BYTES (2 * TILE_M * PITCH * 2)          // 69632 bytes of A+B tiles
#define SMEM_BYTES (SMEM_TILES_BYTES + TILE_N * 4)         // + bias tile

// ---------------- scratch ----------------
__device__ __align__(16) __half g_e_h  [BB * DD];
__device__ __align__(16) float  g_e_f32[BB * DD];
__device__ __align__(16) __half g_W_h  [CC * DD];
__device__ __align__(16) __half g_p_h  [(size_t)BB * CC];   // unnormalized exp(wf), fp16
__device__ __align__(16) float g_partial_p[NT_C * BB];
__device__ __align__(16) float g_partial_q[NT_C * BB];
__device__ float g_rowsum_q[BB];
__device__ float g_inv_p  [BB];
__device__ float g_lossrow[BB];

// ---------------- helpers ----------------
__device__ __forceinline__ uint32_t smem_u32(const void* p) {
    uint32_t a;
    asm("{ .reg .u64 t; cvta.to.shared.u64 t, %1; cvt.u32.u64 %0, t; }" : "=r"(a) : "l"(p));
    return a;
}
__device__ __forceinline__ float warp_sum(float v) {
    #pragma unroll
    for (int o = 16; o; o >>= 1) v += __shfl_xor_sync(0xffffffffu, v, o);
    return v;
}
__device__ __forceinline__ float pow20(float p) {
    float p2 = p * p, p4 = p2 * p2, p8 = p4 * p4, p16 = p8 * p8;
    return p16 * p4;
}
__device__ __forceinline__ void mma16816(float* c, const uint32_t* a, uint32_t b0, uint32_t b1) {
    asm volatile(
        "mma.sync.aligned.m16n8k16.row.col.f32.f16.f16.f32 "
        "{%0,%1,%2,%3}, {%4,%5,%6,%7}, {%8,%9}, {%0,%1,%2,%3};\n"
        : "+f"(c[0]), "+f"(c[1]), "+f"(c[2]), "+f"(c[3])
        : "r"(a[0]), "r"(a[1]), "r"(a[2]), "r"(a[3]), "r"(b0), "r"(b1));
}
__device__ __forceinline__ void ldsm_x4(uint32_t* r, uint32_t addr) {
    asm volatile("ldmatrix.sync.aligned.m8n8.x4.shared.b16 {%0,%1,%2,%3}, [%4];"
                 : "=r"(r[0]), "=r"(r[1]), "=r"(r[2]), "=r"(r[3]) : "r"(addr));
}

// ---------------- K1: normalize x ----------------
__global__ void k_norm_x(const float* __restrict__ x) {
    int warp = (blockIdx.x * blockDim.x + threadIdx.x) >> 5;
    int lane = threadIdx.x & 31;
    if (warp >= BB) return;
    float4 v = ((const float4*)(x + (size_t)warp * DD))[lane];
    float ss = warp_sum(v.x * v.x + v.y * v.y + v.z * v.z + v.w * v.w);
    float inv = 1.0f / fmaxf(sqrtf(ss), 1e-12f);
    float4 e = make_float4(v.x * inv, v.y * inv, v.z * inv, v.w * inv);
    ((float4*)(g_e_f32 + (size_t)warp * DD))[lane] = e;
    __half2* eb = (__half2*)(g_e_h + (size_t)warp * DD);
    eb[lane * 2 + 0] = __floats2half2_rn(e.x, e.y);
    eb[lane * 2 + 1] = __floats2half2_rn(e.z, e.w);
}

// ---------------- K2: normalize W ----------------
__global__ void k_norm_w(const float* __restrict__ W) {
    int warp = (blockIdx.x * blockDim.x + threadIdx.x) >> 5;
    int lane = threadIdx.x & 31;
    if (warp >= CC) return;
    float4 v = ((const float4*)(W + (size_t)warp * DD))[lane];
    float ss = warp_sum(v.x * v.x + v.y * v.y + v.z * v.z + v.w * v.w);
    float inv = 1.0f / fmaxf(sqrtf(ss), 1e-12f);
    __half2* wb = (__half2*)(g_W_h + (size_t)warp * DD);
    wb[lane * 2 + 0] = __floats2half2_rn(v.x * inv, v.y * inv);
    wb[lane * 2 + 1] = __floats2half2_rn(v.z * inv, v.w * inv);
}

// ---------------- K3: single GEMM pass: p(fp16) -> scratch, partials -> scratch ----------------
extern __shared__ char smem_raw[];

__global__ __launch_bounds__(256, 2) void k_gemm(const float* __restrict__ bias) {
    const int tc = blockIdx.x;          // C tile
    const int tm = blockIdx.y;          // B tile
    __half* As = (__half*)smem_raw;
    __half* Bs = As + TILE_M * PITCH;
    float* sBias = (float*)(smem_raw + SMEM_TILES_BYTES);
    const int tid = threadIdx.x;
    const int colBase = tc * TILE_N;

    if (tid < TILE_N) {
        int col = colBase + tid;
        sBias[tid] = (col < CC) ? bias[col] : 0.0f;
    }
    // A tile
    {
        const uint4* gA = (const uint4*)(g_e_h + (size_t)tm * TILE_M * DD);
        #pragma unroll
        for (int i = tid; i < TILE_M * DD / 8; i += 256) {
            int row = i >> 4, seg = i & 15;
            *(uint4*)(As + row * PITCH + seg * 8) = gA[row * 16 + seg];
        }
    }
    // B tile (guarded)
    {
        #pragma unroll
        for (int i = tid; i < TILE_N * DD / 8; i += 256) {
            int row = i >> 4, seg = i & 15;
            int gcol = colBase + row;
            uint4 v = make_uint4(0u, 0u, 0u, 0u);
            if (gcol < CC) v = *(const uint4*)(g_W_h + (size_t)gcol * DD + seg * 8);
            *(uint4*)(Bs + row * PITCH + seg * 8) = v;
        }
    }
    __syncthreads();

    const int wid = tid >> 5, lane = tid & 31;
    const int wm = wid & 3, wn = wid >> 2;   // 4 x 2 warp grid
    const int g = lane >> 2, s = lane & 3;

    const uint32_t sbase = smem_u32(smem_raw);
    const uint32_t aBase = sbase;
    const uint32_t bBase = sbase + TILE_M * PITCH * 2;
    uint32_t aAddr[2], bAddr[4];
    {
        int ar = wm * 32 + (lane & 15);
        int ak = (lane & 16) ? 16 : 0;
        aAddr[0] = aBase + ar * (PITCH * 2) + ak;
        aAddr[1] = aAddr[0] + 16 * (PITCH * 2);
        int brl = (lane & 7) + ((lane & 16) ? 8 : 0);
        int bk  = (lane & 8) ? 16 : 0;
        #pragma unroll
        for (int p = 0; p < 4; p++)
            bAddr[p] = bBase + (wn * 64 + p * 16 + brl) * (PITCH * 2) + bk;
    }

    float acc[2][8][4];
    #pragma unroll
    for (int mt = 0; mt < 2; mt++)
        #pragma unroll
        for (int nt = 0; nt < 8; nt++)
            #pragma unroll
            for (int k = 0; k < 4; k++) acc[mt][nt][k] = 0.0f;

    #pragma unroll
    for (int ks = 0; ks < 8; ks++) {
        const uint32_t koff = ks * 32;
        uint32_t a[2][4], bq[4][4];
        #pragma unroll
        for (int mt = 0; mt < 2; mt++) ldsm_x4(a[mt], aAddr[mt] + koff);
        #pragma unroll
        for (int p = 0; p < 4; p++) ldsm_x4(bq[p], bAddr[p] + koff);
        #pragma unroll
        for (int mt = 0; mt < 2; mt++)
            #pragma unroll
            for (int nt = 0; nt < 8; nt++) {
                int p = nt >> 1;
                if (nt & 1) mma16816(acc[mt][nt], a[mt], bq[p][2], bq[p][3]);
                else        mma16816(acc[mt][nt], a[mt], bq[p][0], bq[p][1]);
            }
    }

    const int rowG = tm * TILE_M + wm * 32;

    // epilogue: p = exp(wf) -> fp16 scratch, accumulate row partials of p, p^20
    float sp[4] = {0, 0, 0, 0}, sq[4] = {0, 0, 0, 0};
    #pragma unroll
    for (int nt = 0; nt < 8; nt++) {
        int cl = wn * 64 + nt * 8 + 2 * s;
        int c0 = colBase + cl;
        if (c0 >= CC) continue;                 // CC even -> pair fully in/out
        float b0v = sBias[cl], b1v = sBias[cl + 1];
        #pragma unroll
        for (int mt = 0; mt < 2; mt++) {
            float p00 = __expf(acc[mt][nt][0] + b0v);
            float p01 = __expf(acc[mt][nt][1] + b1v);
            float p10 = __expf(acc[mt][nt][2] + b0v);
            float p11 = __expf(acc[mt][nt][3] + b1v);
            int r0 = rowG + mt * 16 + g;
            __stcs((__half2*)(g_p_h + (size_t)r0 * CC + c0), __floats2half2_rn(p00, p01));
            __stcs((__half2*)(g_p_h + (size_t)(r0 + 8) * CC + c0), __floats2half2_rn(p10, p11));
            sp[mt * 2 + 0] += p00 + p01;
            sp[mt * 2 + 1] += p10 + p11;
            sq[mt * 2 + 0] += pow20(p00) + pow20(p01);
            sq[mt * 2 + 1] += pow20(p10) + pow20(p11);
        }
    }
    #pragma unroll
    for (int j = 0; j < 4; j++) {
        sp[j] += __shfl_xor_sync(0xffffffffu, sp[j], 1);
        sp[j] += __shfl_xor_sync(0xffffffffu, sp[j], 2);
        sq[j] += __shfl_xor_sync(0xffffffffu, sq[j], 1);
        sq[j] += __shfl_xor_sync(0xffffffffu, sq[j], 2);
    }
    __syncthreads();
    float* sredP = (float*)smem_raw;
    float* sredQ = sredP + 256;
    if (s == 0) {
        #pragma unroll
        for (int mt = 0; mt < 2; mt++)
            #pragma unroll
            for (int h = 0; h < 2; h++) {
                int r = wm * 32 + mt * 16 + g + 8 * h;
                sredP[wn * 128 + r] = sp[mt * 2 + h];
                sredQ[wn * 128 + r] = sq[mt * 2 + h];
            }
    }
    __syncthreads();
    if (tid < 128) {
        g_partial_p[(size_t)tc * BB + tm * TILE_M + tid] = sredP[tid] + sredP[128 + tid];
        g_partial_q[(size_t)tc * BB + tm * TILE_M + tid] = sredQ[tid] + sredQ[128 + tid];
    }
}

// ---------------- K4: coalesced row reduce over C tiles ----------------
// 64 blocks x 256 threads; lane (tid&31) -> row, phase (tid>>5) strides tiles.
__global__ void k_reduce_rows() {
    __shared__ float sP[8][32], sQ[8][32];
    const int rl = threadIdx.x & 31;
    const int ph = threadIdx.x >> 5;
    const int row = blockIdx.x * 32 + rl;
    float sp = 0.0f, sq = 0.0f;
    for (int t = ph; t < NT_C; t += 8) {
        sp += g_partial_p[(size_t)t * BB + row];
        sq += g_partial_q[(size_t)t * BB + row];
    }
    sP[ph][rl] = sp;
    sQ[ph][rl] = sq;
    __syncthreads();
    if (threadIdx.x < 32) {
        float a = 0.0f, b = 0.0f;
        #pragma unroll
        for (int t = 0; t < 8; t++) { a += sP[t][threadIdx.x]; b += sQ[t][threadIdx.x]; }
        g_inv_p[blockIdx.x * 32 + threadIdx.x]    = 1.0f / a;
        g_rowsum_q[blockIdx.x * 32 + threadIdx.x] = b;
    }
}

// ---------------- K5: label margin + per-row loss ----------------
__global__ void k_label(const float* __restrict__ W, const float* __restrict__ bias,
                        const int* __restrict__ labels) {
    int warp = (blockIdx.x * blockDim.x + threadIdx.x) >> 5;
    int lane = threadIdx.x & 31;
    if (warp >= BB) return;
    int l = labels[warp];

    float4 wv = ((const float4*)(W + (size_t)l * DD))[lane];
    float ss = warp_sum(wv.x * wv.x + wv.y * wv.y + wv.z * wv.z + wv.w * wv.w);
    float invn = 1.0f / fmaxf(sqrtf(ss), 1e-12f);

    float4 ev = ((const float4*)(g_e_f32 + (size_t)warp * DD))[lane];
    float d = warp_sum(ev.x * wv.x + ev.y * wv.y + ev.z * wv.z + ev.w * wv.w) * invn;

    const __half2* eb = (const __half2*)(g_e_h + (size_t)warp * DD);
    const __half2* wb = (const __half2*)(g_W_h + (size_t)l * DD);
    float db = 0.0f;
    #pragma unroll
    for (int j = 0; j < 2; j++) {
        float2 e2 = __half22float2(eb[lane * 2 + j]);
        float2 w2 = __half22float2(wb[lane * 2 + j]);
        db += e2.x * w2.x + e2.y * w2.y;
    }
    db = warp_sum(db);

    if (lane == 0) {
        float bl = bias[l];
        float wf_f = d + bl;
        float wf_b = db + bl;
        float cth = fminf(fmaxf(wf_f, -1.0f + CLAMP_EPS), 1.0f - CLAMP_EPS);
        float cm = cth * cosf(MARGIN) - sqrtf(fmaxf(1.0f - cth * cth, 0.0f)) * sinf(MARGIN);
        float Z = g_rowsum_q[warp] - __expf(S_SCALE * wf_b) + __expf(S_SCALE * cm);
        g_lossrow[warp] = logf(Z) - S_SCALE * cm;
    }
}

// ---------------- K6: scale fp16 p -> f32 prediction ----------------
__global__ __launch_bounds__(256) void k_scale(float* __restrict__ out) {
    int idx = blockIdx.x * 256 + threadIdx.x;    // one 4-wide group per thread
    int row = idx / (CC / 4);                    // CC/4 = 12500 groups per row
    float inv = __ldg(&g_inv_p[row]);
    uint2 hv = __ldcs((const uint2*)g_p_h + idx);
    float2 a = __half22float2(*(const __half2*)&hv.x);
    float2 b = __half22float2(*(const __half2*)&hv.y);
    float4 v = make_float4(a.x * inv, a.y * inv, b.x * inv, b.y * inv);
    __stcs((float4*)out + idx, v);
}

// ---------------- K7: finalize loss ----------------
__global__ void k_final(float* __restrict__ out, int out_size) {
    __shared__ float sh[256];
    float v = 0.0f;
    for (int i = threadIdx.x; i < BB; i += 256) v += g_lossrow[i];
    sh[threadIdx.x] = v;
    __syncthreads();
    for (int o = 128; o; o >>= 1) {
        if (threadIdx.x < o) sh[threadIdx.x] += sh[threadIdx.x + o];
        __syncthreads();
    }
    if (threadIdx.x == 0) out[out_size - 1] = sh[0] / (float)BB;
}

// ---------------- launch ----------------
extern "C" void kernel_launch(void* const* d_in, const int* in_sizes, int n_in,
                              void* d_out, int out_size) {
    const float* x      = (const float*)d_in[0];
    const float* W      = (const float*)d_in[1];
    const float* bias   = (const float*)d_in[2];
    const int*   labels = (const int*)d_in[3];
    float* out = (float*)d_out;

    cudaFuncSetAttribute((const void*)k_gemm,
                         cudaFuncAttributeMaxDynamicSharedMemorySize, SMEM_BYTES);

    k_norm_x<<<BB / 8, 256>>>(x);
    k_norm_w<<<(CC + 7) / 8, 256>>>(W);
    k_gemm<<<dim3(NT_C, NT_M), 256, SMEM_BYTES>>>(bias);
    k_reduce_rows<<<BB / 32, 256>>>();
    k_label<<<BB / 8, 256>>>(W, bias, labels);
    k_scale<<<BB * CC / 4 / 256, 256>>>(out);
    k_final<<<1, 256>>>(out, out_size);
}